// round 13
// baseline (speedup 1.0000x reference)
#include <cuda_runtime.h>
#include <cuda_fp16.h>
#include <cstdint>

#define T_STEPS 8640
#define HID     128
#define BATCH   16
#define CSZ     8
#define SLICE   16          /* HID / CSZ */
#define NTH     384
#define FC_TX   128         /* 8 src * 16B packed quad */
#define H1_TX   512         /* 8 src * 64B */
#define PRE_TX  1024        /* 8 src * 128B (fp16 slice) */

// ---------------- PTX helpers ----------------
__device__ __forceinline__ uint32_t smem_u32(const void* p) {
    return (uint32_t)__cvta_generic_to_shared(p);
}
__device__ __forceinline__ uint32_t mapa_rank(uint32_t a, uint32_t r) {
    uint32_t d;
    asm volatile("mapa.shared::cluster.u32 %0, %1, %2;" : "=r"(d) : "r"(a), "r"(r));
    return d;
}
__device__ __forceinline__ void st_async128(uint32_t a, uint4 v, uint32_t mb) {
    asm volatile(
        "st.async.shared::cluster.mbarrier::complete_tx::bytes.v4.b32 "
        "[%0], {%1,%2,%3,%4}, [%5];"
        :: "r"(a), "r"(v.x), "r"(v.y), "r"(v.z), "r"(v.w), "r"(mb) : "memory");
}
__device__ __forceinline__ void mb_init(uint32_t a, uint32_t n) {
    asm volatile("mbarrier.init.shared.b64 [%0], %1;" :: "r"(a), "r"(n) : "memory");
}
__device__ __forceinline__ void mb_expect(uint32_t a, uint32_t tx) {
    asm volatile("mbarrier.arrive.expect_tx.shared.b64 _, [%0], %1;"
                 :: "r"(a), "r"(tx) : "memory");
}
__device__ __forceinline__ void mb_wait(uint32_t a, uint32_t par) {
    asm volatile(
        "{\n\t"
        ".reg .pred P;\n\t"
        "WL_%=:\n\t"
        "mbarrier.try_wait.parity.acquire.cta.shared::cta.b64 P, [%0], %1, 0x989680;\n\t"
        "@P bra.uni WD_%=;\n\t"
        "bra.uni WL_%=;\n\t"
        "WD_%=:\n\t"
        "}"
        :: "r"(a), "r"(par) : "memory");
}
__device__ __forceinline__ void barn(int id, int n) {
    asm volatile("bar.sync %0, %1;" :: "r"(id), "r"(n) : "memory");
}
// single-MUFU transcendentals (~5e-4 local err; LSTM gating damps ~100x)
__device__ __forceinline__ float tanhfast(float x) {
    float r; asm("tanh.approx.f32 %0, %1;" : "=f"(r) : "f"(x)); return r;
}
__device__ __forceinline__ float sigf(float x) {
    return fmaf(tanhfast(0.5f * x), 0.5f, 0.5f);
}

// 64-term dot, 8 accumulators (scalar — best measured variant)
#define DOT64(res, w, hv)                                            \
    {                                                                \
        float a0 = 0.f, a1 = 0.f, a2 = 0.f, a3 = 0.f;                \
        float a4 = 0.f, a5 = 0.f, a6 = 0.f, a7 = 0.f;                \
        _Pragma("unroll")                                            \
        for (int k = 0; k < 8; k++) {                                \
            float4 v0 = (hv)[2 * k], v1 = (hv)[2 * k + 1];           \
            a0 = fmaf((w)[8 * k + 0], v0.x, a0);                     \
            a1 = fmaf((w)[8 * k + 1], v0.y, a1);                     \
            a2 = fmaf((w)[8 * k + 2], v0.z, a2);                     \
            a3 = fmaf((w)[8 * k + 3], v0.w, a3);                     \
            a4 = fmaf((w)[8 * k + 4], v1.x, a4);                     \
            a5 = fmaf((w)[8 * k + 5], v1.y, a5);                     \
            a6 = fmaf((w)[8 * k + 6], v1.z, a6);                     \
            a7 = fmaf((w)[8 * k + 7], v1.w, a7);                     \
        }                                                            \
        res = ((a0 + a1) + (a2 + a3)) + ((a4 + a5) + (a6 + a7));     \
    }

// ---------------- kernel ----------------
// 8-CTA cluster per batch. THREE tx-mbarriers per phase:
//   mb_fc  (8 arrivals/dest)  — gates the step top (critical)
//   mb_h1  (32 arrivals/dest) — waited by grp0, parallel with top (slack)
//   mb_pre (64 arrivals/dest, fp16 payload) — waited by grp1 after y (slack)
// Warp roles:
//   grp0 (warps 0-3):  wait h1 -> g1a = bias + Whh1.h1[p] -> barn1
//   grp1 (warps 4-7):  wait fc -> y -> wait pre -> full local nonlin0 -> s_h0;
//                      barn1; pre(t+1) dot -> fp16 -> broadcast (slack)
//   grp2 (warps 8-11): barn1 -> Wih1.h0 (critical dot) -> g1b -> bar2(128)
//                      -> warp 11: nonlin1, packed fc quad FIRST, then h1
__global__ void __launch_bounds__(NTH, 1) __cluster_dims__(CSZ, 1, 1)
lstm_decoder_kernel(
    const float* __restrict__ y0,
    const float* __restrict__ h0in,
    const float* __restrict__ c0in,
    const float* __restrict__ wih0,
    const float* __restrict__ whh0,
    const float* __restrict__ bih0,
    const float* __restrict__ bhh0,
    const float* __restrict__ wih1,
    const float* __restrict__ whh1,
    const float* __restrict__ bih1,
    const float* __restrict__ bhh1,
    const float* __restrict__ fcw,
    const float* __restrict__ fcb,
    float* __restrict__ out)
{
    __shared__ __align__(16) float  s_h0[2][HID];       // full h0, local
    __shared__ __align__(16) float  s_h1[2][HID];       // full h1, via bcast
    __shared__ __align__(16) __half s_pre_h[2][HID][4]; // FULL pre (fp16)
    __shared__ __align__(16) float  s_g1a[64];
    __shared__ __align__(16) float  s_g1b[2][64];
    __shared__ __align__(16) __half s_prest_h[SLICE][4];// pre slice staging
    __shared__ __align__(16) float  s_h1st[SLICE];
    __shared__ __align__(16) float  s_fcp[2][CSZ][4];
    __shared__ __align__(8) unsigned long long s_mb_fc[2];
    __shared__ __align__(8) unsigned long long s_mb_h1[2];
    __shared__ __align__(8) unsigned long long s_mb_pre[2];

    const int tid  = threadIdx.x;
    const int lane = tid & 31;
    const int wid  = tid >> 5;
    uint32_t rank;
    asm("mov.u32 %0, %%cluster_ctarank;" : "=r"(rank));
    const int b = blockIdx.x >> 3;

    const int grp  = tid >> 7;               // 0:Whh1  1:top/pre  2:Wih1
    const int half = tid & 1;
    const int row  = (tid & 127) >> 1;       // local gate row 0..63
    const int gate = row >> 4;
    const int jloc = row & 15;
    const int grow = gate * HID + (int)rank * SLICE + jloc;

    const uint32_t a_fc0  = smem_u32(&s_mb_fc[0]);
    const uint32_t a_fc1  = smem_u32(&s_mb_fc[1]);
    const uint32_t a_h1_0 = smem_u32(&s_mb_h1[0]);
    const uint32_t a_h1_1 = smem_u32(&s_mb_h1[1]);
    const uint32_t a_pr0  = smem_u32(&s_mb_pre[0]);
    const uint32_t a_pr1  = smem_u32(&s_mb_pre[1]);

    if (tid == 0) {
        mb_init(a_fc0, 1);   mb_init(a_fc1, 1);
        mb_init(a_h1_0, 1);  mb_init(a_h1_1, 1);
        mb_init(a_pr0, 1);   mb_init(a_pr1, 1);
        mb_expect(a_fc0, FC_TX);   mb_expect(a_fc1, FC_TX);
        mb_expect(a_h1_0, H1_TX);  mb_expect(a_h1_1, H1_TX);
        mb_expect(a_pr0, PRE_TX);  mb_expect(a_pr1, PRE_TX);
        #pragma unroll
        for (int i = 0; i < CSZ; i++)
            #pragma unroll
            for (int j = 0; j < 4; j++) s_fcp[0][i][j] = 0.0f;
        s_fcp[0][0][0] = y0[b] - fcb[0];     // iter 0 sees y = y0[b]
    }

    // stage full initial h1
    for (int k = tid; k < HID; k += NTH)
        s_h1[0][k] = h0in[BATCH * HID + b * HID + k];

    // prologue: full pre(0) = bias + Whh0 . h0_init (gmem dot, once, fp16 out)
    for (int r = tid; r < 4 * HID; r += NTH) {
        const int g = r >> 7, j = r & 127;
        const float* wr = whh0 + (size_t)r * HID;
        const float* hv = h0in + b * HID;
        float acc = 0.0f;
        #pragma unroll 8
        for (int k = 0; k < HID; k++) acc = fmaf(wr[k], hv[k], acc);
        s_pre_h[0][j][g] = __float2half_rn(bih0[r] + bhh0[r] + acc);
    }

    // weights (register-resident, 64 floats per thread)
    float w[64];
    {
        const float* Wsrc = (grp == 0) ? whh1 : (grp == 1) ? whh0 : wih1;
        const float* src  = Wsrc + (size_t)grow * HID + half * 64;
        #pragma unroll
        for (int i = 0; i < 64; i++) w[i] = src[i];
    }
    float bias = 0.0f;
    if (half == 0) {
        if (grp == 0)      bias = bih1[grow] + bhh1[grow];
        else if (grp == 1) bias = bih0[grow] + bhh0[grow];
    }

    // grp1 per-lane nonlin0 state: hidden j = tid-128, FULL vector replicated
    float c0r = 0.0f, wi4[4] = {0, 0, 0, 0};
    if (grp == 1) {
        const int j = tid - 128;
        c0r = c0in[b * HID + j];
        #pragma unroll
        for (int g = 0; g < 4; g++) wi4[g] = wih0[g * HID + j];
    }
    // warp-11 nonlin1 state
    float c1r = 0.0f, fcwr = 0.0f;
    if (wid == 11 && lane < SLICE) {
        c1r  = c0in[BATCH * HID + b * HID + (int)rank * SLICE + lane];
        fcwr = fcw[(int)rank * SLICE + lane];
    }
    const float fc_b = fcb[0];

    // ---- precomputed DSMEM destinations ----
    // grp1 pre senders: threads pi<64; dest=((pi>>3)+rank)&7, chunk=pi&7 (16B)
    uint32_t pdst0 = 0, pdst1 = 0, pmbr0 = 0, pmbr1 = 0;
    if (grp == 1) {
        const int pi = tid & 127;
        if (pi < 64) {
            const int pdest = ((pi >> 3) + (int)rank) & 7;
            const uint32_t chunk = (uint32_t)(pi & 7) * 16u;
            pdst0 = mapa_rank(smem_u32(&s_pre_h[0][(int)rank * SLICE][0]) + chunk, pdest);
            pdst1 = mapa_rank(smem_u32(&s_pre_h[1][(int)rank * SLICE][0]) + chunk, pdest);
            pmbr0 = mapa_rank(a_pr0, pdest);
            pmbr1 = mapa_rank(a_pr1, pdest);
        }
    }
    // warp 11: fc packed quad (lanes 0-7, 1 per dest) + h1 slice (all lanes)
    const int qtr = lane & 3;
    uint32_t fcdst0 = 0, fcdst1 = 0, fmbr0 = 0, fmbr1 = 0;
    uint32_t h1dst0 = 0, h1dst1 = 0, h1mbr0 = 0, h1mbr1 = 0;
    if (wid == 11) {
        if (lane < CSZ) {
            const int fdest = (lane + (int)rank) & 7;
            fcdst0 = mapa_rank(smem_u32(&s_fcp[0][rank][0]), fdest);
            fcdst1 = mapa_rank(smem_u32(&s_fcp[1][rank][0]), fdest);
            fmbr0  = mapa_rank(a_fc0, fdest);
            fmbr1  = mapa_rank(a_fc1, fdest);
        }
        const int dest = ((lane >> 2) + (int)rank) & 7;
        h1dst0 = mapa_rank(smem_u32(&s_h1[0][(int)rank * SLICE]) + 16u * qtr, dest);
        h1dst1 = mapa_rank(smem_u32(&s_h1[1][(int)rank * SLICE]) + 16u * qtr, dest);
        h1mbr0 = mapa_rank(a_h1_0, dest);
        h1mbr1 = mapa_rank(a_h1_1, dest);
    }

    __syncthreads();
    asm volatile("barrier.cluster.arrive.aligned;" ::: "memory");
    asm volatile("barrier.cluster.wait.aligned;" ::: "memory");

    for (int t = 0; t < T_STEPS; t++) {
        const int p = t & 1;
        const int q = p ^ 1;
        const uint32_t par = (uint32_t)(((t - 1) >> 1) & 1);

        if (grp == 1) {
            // ======== STEP TOP: fc barrier only (8 arrivals) ========
            if (t > 0) {
                mb_wait(p ? a_fc1 : a_fc0, par);
                if (tid == 128) mb_expect(p ? a_fc1 : a_fc0, FC_TX);
            }
            float y;
            {
                const float4* fv = (const float4*)&s_fcp[p][0][0];
                float4 u0 = fv[0], u1 = fv[1], u2 = fv[2], u3 = fv[3];
                float4 u4 = fv[4], u5 = fv[5], u6 = fv[6], u7 = fv[7];
                float t0 = ((u0.x + u0.y) + (u0.z + u0.w)) + ((u1.x + u1.y) + (u1.z + u1.w));
                float t1 = ((u2.x + u2.y) + (u2.z + u2.w)) + ((u3.x + u3.y) + (u3.z + u3.w));
                float t2 = ((u4.x + u4.y) + (u4.z + u4.w)) + ((u5.x + u5.y) + (u5.z + u5.w));
                float t3 = ((u6.x + u6.y) + (u6.z + u6.w)) + ((u7.x + u7.y) + (u7.z + u7.w));
                y = fc_b + ((t0 + t1) + (t2 + t3));
            }
            if (t > 0 && tid == 128 && rank == 0) out[b * T_STEPS + (t - 1)] = y;
            // pre barrier: sent a full step ago -> near-always complete
            if (t > 0) {
                mb_wait(p ? a_pr1 : a_pr0, par);
                if (tid == 129) mb_expect(p ? a_pr1 : a_pr0, PRE_TX);
            }
            // full local nonlin0: lane j = tid-128 (fp16 pre)
            {
                const int j = tid - 128;
                const __half2* ph = (const __half2*)&s_pre_h[p][j][0];
                float2 f01 = __half22float2(ph[0]);
                float2 f23 = __half22float2(ph[1]);
                float gi = fmaf(wi4[0], y, f01.x);
                float gf = fmaf(wi4[1], y, f01.y);
                float gg = fmaf(wi4[2], y, f23.x);
                float go = fmaf(wi4[3], y, f23.y);
                c0r = sigf(gf) * c0r + sigf(gi) * tanhfast(gg);
                s_h0[p][j] = sigf(go) * tanhfast(c0r);
            }
            barn(1, 384);                    // h0 ready for grp2 / this pre dot
            // ---- pre(t+1) = bias + Whh0 . h0(t); fp16 broadcast (slack) ----
            float d; DOT64(d, w, (const float4*)&s_h0[p][half * 64]);
            float s = bias + d;
            s += __shfl_xor_sync(0xffffffffu, s, 1);
            if (!half) s_prest_h[jloc][gate] = __float2half_rn(s);
            barn(4, 128);                    // grp1 internal
            {
                const int pi = tid & 127;
                if (pi < 64) {
                    uint4 v = ((const uint4*)s_prest_h)[pi & 7];
                    st_async128(q ? pdst1 : pdst0, v, q ? pmbr1 : pmbr0);
                }
            }
        } else if (grp == 0) {
            // ---- g1a = bias + Whh1 . h1[p], PARALLEL with grp1's top ----
            if (t > 0) {
                mb_wait(p ? a_h1_1 : a_h1_0, par);
                if (tid == 0) mb_expect(p ? a_h1_1 : a_h1_0, H1_TX);
            }
            float d; DOT64(d, w, (const float4*)&s_h1[p][half * 64]);
            float s = bias + d;
            s += __shfl_xor_sync(0xffffffffu, s, 1);
            if (!half) s_g1a[row] = s;
            barn(1, 384);                    // publishes g1a (read after bar2)
        } else {
            // ---- Wih1 . h0 (the ONLY critical dot) ----
            barn(1, 384);
            float d; DOT64(d, w, (const float4*)&s_h0[p][half * 64]);
            s_g1b[half][row] = d;
            barn(2, 128);                    // grp2 only

            if (wid == 11) {
                float h1n = 0.0f, fcp = 0.0f;
                if (lane < SLICE) {
                    float gi = s_g1a[lane]      + s_g1b[0][lane]      + s_g1b[1][lane];
                    float gf = s_g1a[16 + lane] + s_g1b[0][16 + lane] + s_g1b[1][16 + lane];
                    float gg = s_g1a[32 + lane] + s_g1b[0][32 + lane] + s_g1b[1][32 + lane];
                    float go = s_g1a[48 + lane] + s_g1b[0][48 + lane] + s_g1b[1][48 + lane];
                    c1r = sigf(gf) * c1r + sigf(gi) * tanhfast(gg);
                    h1n = sigf(go) * tanhfast(c1r);
                    fcp = fcwr * h1n;
                }
                // reduce to quads Q0..Q3 (lanes 0-3), gather packed quad
                fcp += __shfl_xor_sync(0xffffffffu, fcp, 8);
                fcp += __shfl_xor_sync(0xffffffffu, fcp, 4);
                float q0 = __shfl_sync(0xffffffffu, fcp, 0);
                float q1 = __shfl_sync(0xffffffffu, fcp, 1);
                float q2 = __shfl_sync(0xffffffffu, fcp, 2);
                float q3 = __shfl_sync(0xffffffffu, fcp, 3);
                if (lane < CSZ) {            // ONE packed fc quad per dest
                    uint4 v = make_uint4(__float_as_uint(q0), __float_as_uint(q1),
                                         __float_as_uint(q2), __float_as_uint(q3));
                    st_async128(q ? fcdst1 : fcdst0, v, q ? fmbr1 : fmbr0);
                }
                // h1 payload second (slack side, own barrier)
                if (lane < SLICE) s_h1st[lane] = h1n;
                __syncwarp();
                uint4 v = ((const uint4*)s_h1st)[qtr];
                st_async128(q ? h1dst1 : h1dst0, v, q ? h1mbr1 : h1mbr0);
            }
        }
    }

    // final output (fc of iter T-1 landed in buffer 0, parity 1)
    if (rank == 0 && tid == 128) {
        mb_wait(a_fc0, (uint32_t)(((T_STEPS - 1) >> 1) & 1));
        float y = fc_b;
        #pragma unroll
        for (int i = 0; i < CSZ; i++)
            #pragma unroll
            for (int j = 0; j < 4; j++) y += s_fcp[0][i][j];
        out[b * T_STEPS + (T_STEPS - 1)] = y;
    }

    asm volatile("barrier.cluster.arrive.aligned;" ::: "memory");
    asm volatile("barrier.cluster.wait.aligned;" ::: "memory");
}

extern "C" void kernel_launch(void* const* d_in, const int* in_sizes, int n_in,
                              void* d_out, int out_size) {
    (void)in_sizes; (void)n_in; (void)out_size;
    const float* y0    = (const float*)d_in[0];
    const float* h0    = (const float*)d_in[1];
    const float* c0    = (const float*)d_in[2];
    const float* W_ih0 = (const float*)d_in[3];
    const float* W_hh0 = (const float*)d_in[4];
    const float* b_ih0 = (const float*)d_in[5];
    const float* b_hh0 = (const float*)d_in[6];
    const float* W_ih1 = (const float*)d_in[7];
    const float* W_hh1 = (const float*)d_in[8];
    const float* b_ih1 = (const float*)d_in[9];
    const float* b_hh1 = (const float*)d_in[10];
    const float* fc_w  = (const float*)d_in[11];
    const float* fc_b  = (const float*)d_in[12];
    float* out = (float*)d_out;

    lstm_decoder_kernel<<<BATCH * CSZ, NTH>>>(
        y0, h0, c0, W_ih0, W_hh0, b_ih0, b_hh0,
        W_ih1, W_hh1, b_ih1, b_hh1, fc_w, fc_b, out);
}

// round 14
// speedup vs baseline: 1.0356x; 1.0356x over previous
#include <cuda_runtime.h>
#include <cuda_fp16.h>
#include <cstdint>

#define T_STEPS 8640
#define HID     128
#define BATCH   16
#define CSZ     8
#define SLICE   16          /* HID / CSZ */
#define NTH     384
#define TOP_TX  1664        /* fc 8*16B + h1 8*64B + pre(fp16) 8*128B */

// ---------------- PTX helpers ----------------
__device__ __forceinline__ uint32_t smem_u32(const void* p) {
    return (uint32_t)__cvta_generic_to_shared(p);
}
__device__ __forceinline__ uint32_t mapa_rank(uint32_t a, uint32_t r) {
    uint32_t d;
    asm volatile("mapa.shared::cluster.u32 %0, %1, %2;" : "=r"(d) : "r"(a), "r"(r));
    return d;
}
__device__ __forceinline__ void st_async128(uint32_t a, uint4 v, uint32_t mb) {
    asm volatile(
        "st.async.shared::cluster.mbarrier::complete_tx::bytes.v4.b32 "
        "[%0], {%1,%2,%3,%4}, [%5];"
        :: "r"(a), "r"(v.x), "r"(v.y), "r"(v.z), "r"(v.w), "r"(mb) : "memory");
}
__device__ __forceinline__ void mb_init(uint32_t a, uint32_t n) {
    asm volatile("mbarrier.init.shared.b64 [%0], %1;" :: "r"(a), "r"(n) : "memory");
}
__device__ __forceinline__ void mb_expect(uint32_t a, uint32_t tx) {
    asm volatile("mbarrier.arrive.expect_tx.shared.b64 _, [%0], %1;"
                 :: "r"(a), "r"(tx) : "memory");
}
__device__ __forceinline__ void mb_wait(uint32_t a, uint32_t par) {
    asm volatile(
        "{\n\t"
        ".reg .pred P;\n\t"
        "WL_%=:\n\t"
        "mbarrier.try_wait.parity.acquire.cta.shared::cta.b64 P, [%0], %1, 0x989680;\n\t"
        "@P bra.uni WD_%=;\n\t"
        "bra.uni WL_%=;\n\t"
        "WD_%=:\n\t"
        "}"
        :: "r"(a), "r"(par) : "memory");
}
__device__ __forceinline__ void barn(int id, int n) {
    asm volatile("bar.sync %0, %1;" :: "r"(id), "r"(n) : "memory");
}
// single-MUFU transcendentals (~5e-4 local err; LSTM gating damps ~100x)
__device__ __forceinline__ float tanhfast(float x) {
    float r; asm("tanh.approx.f32 %0, %1;" : "=f"(r) : "f"(x)); return r;
}
__device__ __forceinline__ float sigf(float x) {
    return fmaf(tanhfast(0.5f * x), 0.5f, 0.5f);
}

// 64-term dot, 8 accumulators (scalar — best measured variant)
#define DOT64(res, w, hv)                                            \
    {                                                                \
        float a0 = 0.f, a1 = 0.f, a2 = 0.f, a3 = 0.f;                \
        float a4 = 0.f, a5 = 0.f, a6 = 0.f, a7 = 0.f;                \
        _Pragma("unroll")                                            \
        for (int k = 0; k < 8; k++) {                                \
            float4 v0 = (hv)[2 * k], v1 = (hv)[2 * k + 1];           \
            a0 = fmaf((w)[8 * k + 0], v0.x, a0);                     \
            a1 = fmaf((w)[8 * k + 1], v0.y, a1);                     \
            a2 = fmaf((w)[8 * k + 2], v0.z, a2);                     \
            a3 = fmaf((w)[8 * k + 3], v0.w, a3);                     \
            a4 = fmaf((w)[8 * k + 4], v1.x, a4);                     \
            a5 = fmaf((w)[8 * k + 5], v1.y, a5);                     \
            a6 = fmaf((w)[8 * k + 6], v1.z, a6);                     \
            a7 = fmaf((w)[8 * k + 7], v1.w, a7);                     \
        }                                                            \
        res = ((a0 + a1) + (a2 + a3)) + ((a4 + a5) + (a6 + a7));     \
    }

// ---------------- kernel ----------------
// 8-CTA cluster per batch; ONE tx-mbarrier per step top (fc + pre + h1),
// exactly the R11 structure; payloads compacted (fc packed quad, fp16 pre):
// arrivals per dest 192 -> 104.
// Warp roles:
//   grp0 (warps 0-3):  wait top -> g1a = bias + Whh1.h1[p] -> barn1
//   grp1 (warps 4-7):  step top: y, re-arm, full local nonlin0 (fp16 pre) ->
//                      s_h0; barn1; pre(t+1) dot -> fp16 broadcast (slack)
//   grp2 (warps 8-11): barn1 -> Wih1.h0 (critical dot) -> g1b -> bar2(128)
//                      -> warp 11: nonlin1, packed fc quad FIRST, then h1
__global__ void __launch_bounds__(NTH, 1) __cluster_dims__(CSZ, 1, 1)
lstm_decoder_kernel(
    const float* __restrict__ y0,
    const float* __restrict__ h0in,
    const float* __restrict__ c0in,
    const float* __restrict__ wih0,
    const float* __restrict__ whh0,
    const float* __restrict__ bih0,
    const float* __restrict__ bhh0,
    const float* __restrict__ wih1,
    const float* __restrict__ whh1,
    const float* __restrict__ bih1,
    const float* __restrict__ bhh1,
    const float* __restrict__ fcw,
    const float* __restrict__ fcb,
    float* __restrict__ out)
{
    __shared__ __align__(16) float  s_h0[2][HID];       // full h0, local
    __shared__ __align__(16) float  s_h1[2][HID];       // full h1, via bcast
    __shared__ __align__(16) __half s_pre_h[2][HID][4]; // FULL pre (fp16)
    __shared__ __align__(16) float  s_g1a[64];
    __shared__ __align__(16) float  s_g1b[2][64];
    __shared__ __align__(16) __half s_prest_h[SLICE][4];// pre slice staging
    __shared__ __align__(16) float  s_h1st[SLICE];
    __shared__ __align__(16) float  s_fcp[2][CSZ][4];
    __shared__ __align__(8) unsigned long long s_mb_top[2];

    const int tid  = threadIdx.x;
    const int lane = tid & 31;
    const int wid  = tid >> 5;
    uint32_t rank;
    asm("mov.u32 %0, %%cluster_ctarank;" : "=r"(rank));
    const int b = blockIdx.x >> 3;

    const int grp  = tid >> 7;               // 0:Whh1  1:top/pre  2:Wih1
    const int half = tid & 1;
    const int row  = (tid & 127) >> 1;       // local gate row 0..63
    const int gate = row >> 4;
    const int jloc = row & 15;
    const int grow = gate * HID + (int)rank * SLICE + jloc;

    const uint32_t a_top0 = smem_u32(&s_mb_top[0]);
    const uint32_t a_top1 = smem_u32(&s_mb_top[1]);

    if (tid == 0) {
        mb_init(a_top0, 1);  mb_init(a_top1, 1);
        mb_expect(a_top0, TOP_TX);  mb_expect(a_top1, TOP_TX);
        #pragma unroll
        for (int i = 0; i < CSZ; i++)
            #pragma unroll
            for (int j = 0; j < 4; j++) s_fcp[0][i][j] = 0.0f;
        s_fcp[0][0][0] = y0[b] - fcb[0];     // iter 0 sees y = y0[b]
    }

    // stage full initial h1
    for (int k = tid; k < HID; k += NTH)
        s_h1[0][k] = h0in[BATCH * HID + b * HID + k];

    // prologue: full pre(0) = bias + Whh0 . h0_init (gmem dot, once, fp16 out)
    for (int r = tid; r < 4 * HID; r += NTH) {
        const int g = r >> 7, j = r & 127;
        const float* wr = whh0 + (size_t)r * HID;
        const float* hv = h0in + b * HID;
        float acc = 0.0f;
        #pragma unroll 8
        for (int k = 0; k < HID; k++) acc = fmaf(wr[k], hv[k], acc);
        s_pre_h[0][j][g] = __float2half_rn(bih0[r] + bhh0[r] + acc);
    }

    // weights (register-resident, 64 floats per thread)
    float w[64];
    {
        const float* Wsrc = (grp == 0) ? whh1 : (grp == 1) ? whh0 : wih1;
        const float* src  = Wsrc + (size_t)grow * HID + half * 64;
        #pragma unroll
        for (int i = 0; i < 64; i++) w[i] = src[i];
    }
    float bias = 0.0f;
    if (half == 0) {
        if (grp == 0)      bias = bih1[grow] + bhh1[grow];
        else if (grp == 1) bias = bih0[grow] + bhh0[grow];
    }

    // grp1 per-lane nonlin0 state: hidden j = tid-128, FULL vector replicated
    float c0r = 0.0f, wi4[4] = {0, 0, 0, 0};
    if (grp == 1) {
        const int j = tid - 128;
        c0r = c0in[b * HID + j];
        #pragma unroll
        for (int g = 0; g < 4; g++) wi4[g] = wih0[g * HID + j];
    }
    // warp-11 nonlin1 state
    float c1r = 0.0f, fcwr = 0.0f;
    if (wid == 11 && lane < SLICE) {
        c1r  = c0in[BATCH * HID + b * HID + (int)rank * SLICE + lane];
        fcwr = fcw[(int)rank * SLICE + lane];
    }
    const float fc_b = fcb[0];

    // ---- precomputed DSMEM destinations ----
    // grp1 pre senders: pi = tid&127 < 64; dest=((pi>>3)+rank)&7, chunk=pi&7
    uint32_t pdst0 = 0, pdst1 = 0, pmbr0 = 0, pmbr1 = 0;
    if (grp == 1) {
        const int pi = tid & 127;
        if (pi < 64) {
            const int pdest = ((pi >> 3) + (int)rank) & 7;
            const uint32_t chunk = (uint32_t)(pi & 7) * 16u;
            pdst0 = mapa_rank(smem_u32(&s_pre_h[0][(int)rank * SLICE][0]) + chunk, pdest);
            pdst1 = mapa_rank(smem_u32(&s_pre_h[1][(int)rank * SLICE][0]) + chunk, pdest);
            pmbr0 = mapa_rank(a_top0, pdest);
            pmbr1 = mapa_rank(a_top1, pdest);
        }
    }
    // warp 11: fc packed quad (lanes 0-7, one per dest) + h1 slice (all lanes)
    const int qtr = lane & 3;
    uint32_t fcdst0 = 0, fcdst1 = 0, fmbr0 = 0, fmbr1 = 0;
    uint32_t h1dst0 = 0, h1dst1 = 0, tmbr0 = 0, tmbr1 = 0;
    if (wid == 11) {
        if (lane < CSZ) {
            const int fdest = (lane + (int)rank) & 7;
            fcdst0 = mapa_rank(smem_u32(&s_fcp[0][rank][0]), fdest);
            fcdst1 = mapa_rank(smem_u32(&s_fcp[1][rank][0]), fdest);
            fmbr0  = mapa_rank(a_top0, fdest);
            fmbr1  = mapa_rank(a_top1, fdest);
        }
        const int dest = ((lane >> 2) + (int)rank) & 7;
        h1dst0 = mapa_rank(smem_u32(&s_h1[0][(int)rank * SLICE]) + 16u * qtr, dest);
        h1dst1 = mapa_rank(smem_u32(&s_h1[1][(int)rank * SLICE]) + 16u * qtr, dest);
        tmbr0  = mapa_rank(a_top0, dest);
        tmbr1  = mapa_rank(a_top1, dest);
    }

    __syncthreads();
    asm volatile("barrier.cluster.arrive.aligned;" ::: "memory");
    asm volatile("barrier.cluster.wait.aligned;" ::: "memory");

    for (int t = 0; t < T_STEPS; t++) {
        const int p = t & 1;
        const int q = p ^ 1;
        const uint32_t a_topp = p ? a_top1 : a_top0;
        const uint32_t par    = (uint32_t)(((t - 1) >> 1) & 1);

        if (grp == 1) {
            // ======== STEP TOP (ONE wait: fc + pre + h1 all arrived) ========
            if (t > 0) {
                mb_wait(a_topp, par);
                if (tid == 128) mb_expect(a_topp, TOP_TX);   // fresh phase
            }
            float y;
            {
                const float4* fv = (const float4*)&s_fcp[p][0][0];
                float4 u0 = fv[0], u1 = fv[1], u2 = fv[2], u3 = fv[3];
                float4 u4 = fv[4], u5 = fv[5], u6 = fv[6], u7 = fv[7];
                float t0 = ((u0.x + u0.y) + (u0.z + u0.w)) + ((u1.x + u1.y) + (u1.z + u1.w));
                float t1 = ((u2.x + u2.y) + (u2.z + u2.w)) + ((u3.x + u3.y) + (u3.z + u3.w));
                float t2 = ((u4.x + u4.y) + (u4.z + u4.w)) + ((u5.x + u5.y) + (u5.z + u5.w));
                float t3 = ((u6.x + u6.y) + (u6.z + u6.w)) + ((u7.x + u7.y) + (u7.z + u7.w));
                y = fc_b + ((t0 + t1) + (t2 + t3));
            }
            if (t > 0 && tid == 128 && rank == 0) out[b * T_STEPS + (t - 1)] = y;
            // full local nonlin0: lane j = tid-128 (fp16 pre)
            {
                const int j = tid - 128;
                const __half2* ph = (const __half2*)&s_pre_h[p][j][0];
                float2 f01 = __half22float2(ph[0]);
                float2 f23 = __half22float2(ph[1]);
                float gi = fmaf(wi4[0], y, f01.x);
                float gf = fmaf(wi4[1], y, f01.y);
                float gg = fmaf(wi4[2], y, f23.x);
                float go = fmaf(wi4[3], y, f23.y);
                c0r = sigf(gf) * c0r + sigf(gi) * tanhfast(gg);
                s_h0[p][j] = sigf(go) * tanhfast(c0r);
            }
            barn(1, 384);                    // h0 ready for grp2 / this pre dot
            // ---- pre(t+1) = bias + Whh0 . h0(t); fp16 broadcast (slack) ----
            float d; DOT64(d, w, (const float4*)&s_h0[p][half * 64]);
            float s = bias + d;
            s += __shfl_xor_sync(0xffffffffu, s, 1);
            if (!half) s_prest_h[jloc][gate] = __float2half_rn(s);
            barn(4, 128);                    // grp1 internal
            {
                const int pi = tid & 127;
                if (pi < 64) {
                    uint4 v = ((const uint4*)s_prest_h)[pi & 7];
                    st_async128(q ? pdst1 : pdst0, v, q ? pmbr1 : pmbr0);
                }
            }
        } else if (grp == 0) {
            // ---- g1a = bias + Whh1 . h1[p], PARALLEL with grp1's top ----
            if (t > 0) mb_wait(a_topp, par);
            float d; DOT64(d, w, (const float4*)&s_h1[p][half * 64]);
            float s = bias + d;
            s += __shfl_xor_sync(0xffffffffu, s, 1);
            if (!half) s_g1a[row] = s;
            barn(1, 384);                    // publishes g1a (read after bar2)
        } else {
            // ---- Wih1 . h0 (the ONLY critical dot) ----
            barn(1, 384);
            float d; DOT64(d, w, (const float4*)&s_h0[p][half * 64]);
            s_g1b[half][row] = d;
            barn(2, 128);                    // grp2 only

            if (wid == 11) {
                float h1n = 0.0f, fcp = 0.0f;
                if (lane < SLICE) {
                    float gi = s_g1a[lane]      + s_g1b[0][lane]      + s_g1b[1][lane];
                    float gf = s_g1a[16 + lane] + s_g1b[0][16 + lane] + s_g1b[1][16 + lane];
                    float gg = s_g1a[32 + lane] + s_g1b[0][32 + lane] + s_g1b[1][32 + lane];
                    float go = s_g1a[48 + lane] + s_g1b[0][48 + lane] + s_g1b[1][48 + lane];
                    c1r = sigf(gf) * c1r + sigf(gi) * tanhfast(gg);
                    h1n = sigf(go) * tanhfast(c1r);
                    fcp = fcwr * h1n;
                }
                // reduce to quads Q0..Q3 (lanes 0-3), gather into packed quad
                fcp += __shfl_xor_sync(0xffffffffu, fcp, 8);
                fcp += __shfl_xor_sync(0xffffffffu, fcp, 4);
                float q0 = __shfl_sync(0xffffffffu, fcp, 0);
                float q1 = __shfl_sync(0xffffffffu, fcp, 1);
                float q2 = __shfl_sync(0xffffffffu, fcp, 2);
                float q3 = __shfl_sync(0xffffffffu, fcp, 3);
                if (lane < CSZ) {            // ONE packed fc quad per dest
                    uint4 v = make_uint4(__float_as_uint(q0), __float_as_uint(q1),
                                         __float_as_uint(q2), __float_as_uint(q3));
                    st_async128(q ? fcdst1 : fcdst0, v, q ? fmbr1 : fmbr0);
                }
                // h1 payload second (slack side)
                if (lane < SLICE) s_h1st[lane] = h1n;
                __syncwarp();
                uint4 v = ((const uint4*)s_h1st)[qtr];
                st_async128(q ? h1dst1 : h1dst0, v, q ? tmbr1 : tmbr0);
            }
        }
    }

    // final output (fc of iter T-1 landed in buffer 0, parity 1)
    if (rank == 0 && tid == 128) {
        mb_wait(a_top0, (uint32_t)(((T_STEPS - 1) >> 1) & 1));
        float y = fc_b;
        #pragma unroll
        for (int i = 0; i < CSZ; i++)
            #pragma unroll
            for (int j = 0; j < 4; j++) y += s_fcp[0][i][j];
        out[b * T_STEPS + (T_STEPS - 1)] = y;
    }

    asm volatile("barrier.cluster.arrive.aligned;" ::: "memory");
    asm volatile("barrier.cluster.wait.aligned;" ::: "memory");
}

extern "C" void kernel_launch(void* const* d_in, const int* in_sizes, int n_in,
                              void* d_out, int out_size) {
    (void)in_sizes; (void)n_in; (void)out_size;
    const float* y0    = (const float*)d_in[0];
    const float* h0    = (const float*)d_in[1];
    const float* c0    = (const float*)d_in[2];
    const float* W_ih0 = (const float*)d_in[3];
    const float* W_hh0 = (const float*)d_in[4];
    const float* b_ih0 = (const float*)d_in[5];
    const float* b_hh0 = (const float*)d_in[6];
    const float* W_ih1 = (const float*)d_in[7];
    const float* W_hh1 = (const float*)d_in[8];
    const float* b_ih1 = (const float*)d_in[9];
    const float* b_hh1 = (const float*)d_in[10];
    const float* fc_w  = (const float*)d_in[11];
    const float* fc_b  = (const float*)d_in[12];
    float* out = (float*)d_out;

    lstm_decoder_kernel<<<BATCH * CSZ, NTH>>>(
        y0, h0, c0, W_ih0, W_hh0, b_ih0, b_hh0,
        W_ih1, W_hh1, b_ih1, b_hh1, fc_w, fc_b, out);
}

// round 15
// speedup vs baseline: 1.1091x; 1.0709x over previous
#include <cuda_runtime.h>
#include <cstdint>

#define T_STEPS 8640
#define HID     128
#define BATCH   16
#define CSZ     8
#define SLICE   16          /* HID / CSZ */
#define NTH     384
#define TOP_TX  2688        /* fc 8*4*4B + pre 8*64*4B + h1 8*16*4B */

// ---------------- PTX helpers ----------------
__device__ __forceinline__ uint32_t smem_u32(const void* p) {
    return (uint32_t)__cvta_generic_to_shared(p);
}
__device__ __forceinline__ uint32_t mapa_rank(uint32_t a, uint32_t r) {
    uint32_t d;
    asm volatile("mapa.shared::cluster.u32 %0, %1, %2;" : "=r"(d) : "r"(a), "r"(r));
    return d;
}
__device__ __forceinline__ void st_async128(uint32_t a, uint4 v, uint32_t mb) {
    asm volatile(
        "st.async.shared::cluster.mbarrier::complete_tx::bytes.v4.b32 "
        "[%0], {%1,%2,%3,%4}, [%5];"
        :: "r"(a), "r"(v.x), "r"(v.y), "r"(v.z), "r"(v.w), "r"(mb) : "memory");
}
__device__ __forceinline__ void st_async32(uint32_t a, uint32_t v, uint32_t mb) {
    asm volatile("st.async.shared::cluster.mbarrier::complete_tx::bytes.b32 [%0], %1, [%2];"
                 :: "r"(a), "r"(v), "r"(mb) : "memory");
}
__device__ __forceinline__ void mb_init(uint32_t a, uint32_t n) {
    asm volatile("mbarrier.init.shared.b64 [%0], %1;" :: "r"(a), "r"(n) : "memory");
}
__device__ __forceinline__ void mb_expect(uint32_t a, uint32_t tx) {
    asm volatile("mbarrier.arrive.expect_tx.shared.b64 _, [%0], %1;"
                 :: "r"(a), "r"(tx) : "memory");
}
__device__ __forceinline__ void mb_wait(uint32_t a, uint32_t par) {
    asm volatile(
        "{\n\t"
        ".reg .pred P;\n\t"
        "WL_%=:\n\t"
        "mbarrier.try_wait.parity.acquire.cta.shared::cta.b64 P, [%0], %1, 0x989680;\n\t"
        "@P bra.uni WD_%=;\n\t"
        "bra.uni WL_%=;\n\t"
        "WD_%=:\n\t"
        "}"
        :: "r"(a), "r"(par) : "memory");
}
__device__ __forceinline__ void barn(int id, int n) {
    asm volatile("bar.sync %0, %1;" :: "r"(id), "r"(n) : "memory");
}
// single-MUFU transcendentals (~5e-4 local err; LSTM gating damps ~100x)
__device__ __forceinline__ float tanhfast(float x) {
    float r; asm("tanh.approx.f32 %0, %1;" : "=f"(r) : "f"(x)); return r;
}
__device__ __forceinline__ float sigf(float x) {
    return fmaf(tanhfast(0.5f * x), 0.5f, 0.5f);
}

// 64-term dot, 8 accumulators (scalar — best measured variant)
#define DOT64(res, w, hv)                                            \
    {                                                                \
        float a0 = 0.f, a1 = 0.f, a2 = 0.f, a3 = 0.f;                \
        float a4 = 0.f, a5 = 0.f, a6 = 0.f, a7 = 0.f;                \
        _Pragma("unroll")                                            \
        for (int k = 0; k < 8; k++) {                                \
            float4 v0 = (hv)[2 * k], v1 = (hv)[2 * k + 1];           \
            a0 = fmaf((w)[8 * k + 0], v0.x, a0);                     \
            a1 = fmaf((w)[8 * k + 1], v0.y, a1);                     \
            a2 = fmaf((w)[8 * k + 2], v0.z, a2);                     \
            a3 = fmaf((w)[8 * k + 3], v0.w, a3);                     \
            a4 = fmaf((w)[8 * k + 4], v1.x, a4);                     \
            a5 = fmaf((w)[8 * k + 5], v1.y, a5);                     \
            a6 = fmaf((w)[8 * k + 6], v1.z, a6);                     \
            a7 = fmaf((w)[8 * k + 7], v1.w, a7);                     \
        }                                                            \
        res = ((a0 + a1) + (a2 + a3)) + ((a4 + a5) + (a6 + a7));     \
    }

// ---------------- kernel ----------------
// 8-CTA cluster per batch; ONE tx-mbarrier per step top (fc + pre + h1).
// R11 structure with two chain cuts: g1a/g1b stored [j][gate] (warp11 reads
// 3x LDS.128), and grp0 publishes g1a via bar2 so barn1 is only 256 wide.
// Warp roles:
//   grp0 (warps 0-3):  wait top -> g1a = bias + Whh1.h1[p] -> bar2(256)
//   grp1 (warps 4-7):  step top: y, re-arm, full local nonlin0 -> s_h0;
//                      barn1(256); pre(t+1) dot -> broadcast (slack)
//   grp2 (warps 8-11): barn1(256) -> Wih1.h0 (critical dot) -> g1b ->
//                      bar2(256) -> warp11: nonlin1, fc FIRST, then h1
__global__ void __launch_bounds__(NTH, 1) __cluster_dims__(CSZ, 1, 1)
lstm_decoder_kernel(
    const float* __restrict__ y0,
    const float* __restrict__ h0in,
    const float* __restrict__ c0in,
    const float* __restrict__ wih0,
    const float* __restrict__ whh0,
    const float* __restrict__ bih0,
    const float* __restrict__ bhh0,
    const float* __restrict__ wih1,
    const float* __restrict__ whh1,
    const float* __restrict__ bih1,
    const float* __restrict__ bhh1,
    const float* __restrict__ fcw,
    const float* __restrict__ fcb,
    float* __restrict__ out)
{
    __shared__ __align__(16) float s_h0[2][HID];        // full h0, local
    __shared__ __align__(16) float s_h1[2][HID];        // full h1, via bcast
    __shared__ __align__(16) float s_pre[2][HID][4];    // FULL pre-activations
    __shared__ __align__(16) float s_g1a[SLICE][4];     // [j][gate] (grp0)
    __shared__ __align__(16) float s_g1b[2][SLICE][4];  // [half][j][gate] (grp2)
    __shared__ __align__(16) float s_prest[SLICE][4];   // pre slice staging
    __shared__ __align__(16) float s_h1st[SLICE];
    __shared__ __align__(16) float s_fcp[2][CSZ][4];
    __shared__ __align__(8) unsigned long long s_mb_top[2];

    const int tid  = threadIdx.x;
    const int lane = tid & 31;
    const int wid  = tid >> 5;
    uint32_t rank;
    asm("mov.u32 %0, %%cluster_ctarank;" : "=r"(rank));
    const int b = blockIdx.x >> 3;

    const int grp  = tid >> 7;               // 0:Whh1  1:top/pre  2:Wih1
    const int half = tid & 1;
    const int row  = (tid & 127) >> 1;       // local gate row 0..63
    const int gate = row >> 4;
    const int jloc = row & 15;
    const int grow = gate * HID + (int)rank * SLICE + jloc;

    const uint32_t a_top0 = smem_u32(&s_mb_top[0]);
    const uint32_t a_top1 = smem_u32(&s_mb_top[1]);

    if (tid == 0) {
        mb_init(a_top0, 1);  mb_init(a_top1, 1);
        mb_expect(a_top0, TOP_TX);  mb_expect(a_top1, TOP_TX);
        #pragma unroll
        for (int i = 0; i < CSZ; i++)
            #pragma unroll
            for (int j = 0; j < 4; j++) s_fcp[0][i][j] = 0.0f;
        s_fcp[0][0][0] = y0[b] - fcb[0];     // iter 0 sees y = y0[b]
    }

    // stage full initial h1
    for (int k = tid; k < HID; k += NTH)
        s_h1[0][k] = h0in[BATCH * HID + b * HID + k];

    // prologue: full pre(0) = bias + Whh0 . h0_init (gmem dot, once)
    for (int r = tid; r < 4 * HID; r += NTH) {
        const int g = r >> 7, j = r & 127;
        const float* wr = whh0 + (size_t)r * HID;
        const float* hv = h0in + b * HID;
        float acc = 0.0f;
        #pragma unroll 8
        for (int k = 0; k < HID; k++) acc = fmaf(wr[k], hv[k], acc);
        s_pre[0][j][g] = bih0[r] + bhh0[r] + acc;
    }

    // weights (register-resident, 64 floats per thread)
    float w[64];
    {
        const float* Wsrc = (grp == 0) ? whh1 : (grp == 1) ? whh0 : wih1;
        const float* src  = Wsrc + (size_t)grow * HID + half * 64;
        #pragma unroll
        for (int i = 0; i < 64; i++) w[i] = src[i];
    }
    float bias = 0.0f;
    if (half == 0) {
        if (grp == 0)      bias = bih1[grow] + bhh1[grow];
        else if (grp == 1) bias = bih0[grow] + bhh0[grow];
    }

    // grp1 per-lane nonlin0 state: hidden j = tid-128, FULL vector replicated
    float c0r = 0.0f, wi4[4] = {0, 0, 0, 0};
    if (grp == 1) {
        const int j = tid - 128;
        c0r = c0in[b * HID + j];
        #pragma unroll
        for (int g = 0; g < 4; g++) wi4[g] = wih0[g * HID + j];
    }
    // warp-11 nonlin1 state
    float c1r = 0.0f, fcwr = 0.0f;
    if (wid == 11 && lane < SLICE) {
        c1r  = c0in[BATCH * HID + b * HID + (int)rank * SLICE + lane];
        fcwr = fcw[(int)rank * SLICE + lane];
    }
    const float fc_b = fcb[0];

    // ---- precomputed DSMEM destinations ----
    // grp1: pre slice — thread i=tid&127: dest=((i>>4)+rank)&7, jj=i&15
    uint32_t pdst0 = 0, pdst1 = 0, pmbr0 = 0, pmbr1 = 0;
    if (grp == 1) {
        const int pi    = tid & 127;
        const int pdest = ((pi >> 4) + (int)rank) & 7;
        const int jj    = pi & 15;
        pdst0 = mapa_rank(smem_u32(&s_pre[0][(int)rank * SLICE + jj][0]), pdest);
        pdst1 = mapa_rank(smem_u32(&s_pre[1][(int)rank * SLICE + jj][0]), pdest);
        pmbr0 = mapa_rank(a_top0, pdest);
        pmbr1 = mapa_rank(a_top1, pdest);
    }
    // warp 11: fc + h1 slice — lane: dest=((lane>>2)+rank)&7, qtr=lane&3
    const int dest = ((lane >> 2) + (int)rank) & 7;
    const int qtr  = lane & 3;
    uint32_t fcdst0 = 0, fcdst1 = 0, h1dst0 = 0, h1dst1 = 0, tmbr0 = 0, tmbr1 = 0;
    if (wid == 11) {
        fcdst0 = mapa_rank(smem_u32(&s_fcp[0][rank][qtr]), dest);
        fcdst1 = mapa_rank(smem_u32(&s_fcp[1][rank][qtr]), dest);
        h1dst0 = mapa_rank(smem_u32(&s_h1[0][(int)rank * SLICE]) + 16u * qtr, dest);
        h1dst1 = mapa_rank(smem_u32(&s_h1[1][(int)rank * SLICE]) + 16u * qtr, dest);
        tmbr0  = mapa_rank(a_top0, dest);
        tmbr1  = mapa_rank(a_top1, dest);
    }

    __syncthreads();
    asm volatile("barrier.cluster.arrive.aligned;" ::: "memory");
    asm volatile("barrier.cluster.wait.aligned;" ::: "memory");

    for (int t = 0; t < T_STEPS; t++) {
        const int p = t & 1;
        const int q = p ^ 1;
        const uint32_t a_topp = p ? a_top1 : a_top0;
        const uint32_t par    = (uint32_t)(((t - 1) >> 1) & 1);

        if (grp == 1) {
            // ======== STEP TOP (one wait: fc + pre + h1 all arrived) ========
            if (t > 0) {
                mb_wait(a_topp, par);
                if (tid == 128) mb_expect(a_topp, TOP_TX);   // fresh phase
            }
            float y;
            {
                const float4* fv = (const float4*)&s_fcp[p][0][0];
                float4 u0 = fv[0], u1 = fv[1], u2 = fv[2], u3 = fv[3];
                float4 u4 = fv[4], u5 = fv[5], u6 = fv[6], u7 = fv[7];
                float t0 = ((u0.x + u0.y) + (u0.z + u0.w)) + ((u1.x + u1.y) + (u1.z + u1.w));
                float t1 = ((u2.x + u2.y) + (u2.z + u2.w)) + ((u3.x + u3.y) + (u3.z + u3.w));
                float t2 = ((u4.x + u4.y) + (u4.z + u4.w)) + ((u5.x + u5.y) + (u5.z + u5.w));
                float t3 = ((u6.x + u6.y) + (u6.z + u6.w)) + ((u7.x + u7.y) + (u7.z + u7.w));
                y = fc_b + ((t0 + t1) + (t2 + t3));
            }
            if (t > 0 && tid == 128 && rank == 0) out[b * T_STEPS + (t - 1)] = y;
            // full local nonlin0: lane j = tid-128
            {
                const int j = tid - 128;
                const float4 pg = *(const float4*)&s_pre[p][j][0];
                float gi = fmaf(wi4[0], y, pg.x);
                float gf = fmaf(wi4[1], y, pg.y);
                float gg = fmaf(wi4[2], y, pg.z);
                float go = fmaf(wi4[3], y, pg.w);
                c0r = sigf(gf) * c0r + sigf(gi) * tanhfast(gg);
                s_h0[p][j] = sigf(go) * tanhfast(c0r);
            }
            barn(1, 256);                    // grp1+grp2: h0 ready
            // ---- pre(t+1) = bias + Whh0 . h0(t); broadcast (slack side) ----
            float d; DOT64(d, w, (const float4*)&s_h0[p][half * 64]);
            float s = bias + d;
            s += __shfl_xor_sync(0xffffffffu, s, 1);
            if (!half) s_prest[jloc][gate] = s;
            barn(4, 128);                    // grp1 internal
            uint4 v = ((const uint4*)s_prest)[tid & 15];
            st_async128(q ? pdst1 : pdst0, v, q ? pmbr1 : pmbr0);
        } else if (grp == 0) {
            // ---- g1a = bias + Whh1 . h1[p], PARALLEL with grp1's top ----
            if (t > 0) mb_wait(a_topp, par);
            float d; DOT64(d, w, (const float4*)&s_h1[p][half * 64]);
            float s = bias + d;
            s += __shfl_xor_sync(0xffffffffu, s, 1);
            if (!half) s_g1a[jloc][gate] = s;
            barn(2, 256);                    // publishes g1a to warp11 (early)
        } else {
            // ---- Wih1 . h0 (the ONLY critical dot) ----
            barn(1, 256);
            float d; DOT64(d, w, (const float4*)&s_h0[p][half * 64]);
            s_g1b[half][jloc][gate] = d;
            barn(2, 256);                    // grp0 (long arrived) + grp2

            if (wid == 11) {
                float h1n = 0.0f, fcp = 0.0f;
                if (lane < SLICE) {
                    const float4 A  = *(const float4*)&s_g1a[lane][0];
                    const float4 B0 = *(const float4*)&s_g1b[0][lane][0];
                    const float4 B1 = *(const float4*)&s_g1b[1][lane][0];
                    float gi = A.x + B0.x + B1.x;
                    float gf = A.y + B0.y + B1.y;
                    float gg = A.z + B0.z + B1.z;
                    float go = A.w + B0.w + B1.w;
                    c1r = sigf(gf) * c1r + sigf(gi) * tanhfast(gg);
                    h1n = sigf(go) * tanhfast(c1r);
                    fcp = fcwr * h1n;
                }
                // 3-shfl partial reduce; every lane ends with S[lane&3]
                fcp += __shfl_xor_sync(0xffffffffu, fcp, 8);
                fcp += __shfl_xor_sync(0xffffffffu, fcp, 4);
                fcp  = __shfl_sync(0xffffffffu, fcp, lane & 3);
                // fc partials sent FIRST (critical payload for t+1)
                st_async32(q ? fcdst1 : fcdst0, __float_as_uint(fcp),
                           q ? tmbr1 : tmbr0);
                // h1 payload second (slack side)
                if (lane < SLICE) s_h1st[lane] = h1n;
                __syncwarp();
                uint4 v = ((const uint4*)s_h1st)[qtr];
                st_async128(q ? h1dst1 : h1dst0, v, q ? tmbr1 : tmbr0);
            }
        }
    }

    // final output (fc of iter T-1 landed in buffer 0, parity 1)
    if (rank == 0 && tid == 128) {
        mb_wait(a_top0, (uint32_t)(((T_STEPS - 1) >> 1) & 1));
        float y = fc_b;
        #pragma unroll
        for (int i = 0; i < CSZ; i++)
            #pragma unroll
            for (int j = 0; j < 4; j++) y += s_fcp[0][i][j];
        out[b * T_STEPS + (T_STEPS - 1)] = y;
    }

    asm volatile("barrier.cluster.arrive.aligned;" ::: "memory");
    asm volatile("barrier.cluster.wait.aligned;" ::: "memory");
}

extern "C" void kernel_launch(void* const* d_in, const int* in_sizes, int n_in,
                              void* d_out, int out_size) {
    (void)in_sizes; (void)n_in; (void)out_size;
    const float* y0    = (const float*)d_in[0];
    const float* h0    = (const float*)d_in[1];
    const float* c0    = (const float*)d_in[2];
    const float* W_ih0 = (const float*)d_in[3];
    const float* W_hh0 = (const float*)d_in[4];
    const float* b_ih0 = (const float*)d_in[5];
    const float* b_hh0 = (const float*)d_in[6];
    const float* W_ih1 = (const float*)d_in[7];
    const float* W_hh1 = (const float*)d_in[8];
    const float* b_ih1 = (const float*)d_in[9];
    const float* b_hh1 = (const float*)d_in[10];
    const float* fc_w  = (const float*)d_in[11];
    const float* fc_b  = (const float*)d_in[12];
    float* out = (float*)d_out;

    lstm_decoder_kernel<<<BATCH * CSZ, NTH>>>(
        y0, h0, c0, W_ih0, W_hh0, b_ih0, b_hh0,
        W_ih1, W_hh1, b_ih1, b_hh1, fc_w, fc_b, out);
}

// round 16
// speedup vs baseline: 1.1831x; 1.0667x over previous
#include <cuda_runtime.h>
#include <cstdint>

#define T_STEPS 8640
#define HID     128
#define BATCH   16
#define CSZ     8
#define SLICE   16          /* HID / CSZ */
#define NTH     384
#define TOP_TX  2688        /* fc 8*4*4B + pre 8*64*4B + h1 8*16*4B */

// ---------------- PTX helpers ----------------
__device__ __forceinline__ uint32_t smem_u32(const void* p) {
    return (uint32_t)__cvta_generic_to_shared(p);
}
__device__ __forceinline__ uint32_t mapa_rank(uint32_t a, uint32_t r) {
    uint32_t d;
    asm volatile("mapa.shared::cluster.u32 %0, %1, %2;" : "=r"(d) : "r"(a), "r"(r));
    return d;
}
__device__ __forceinline__ void st_async128(uint32_t a, uint4 v, uint32_t mb) {
    asm volatile(
        "st.async.shared::cluster.mbarrier::complete_tx::bytes.v4.b32 "
        "[%0], {%1,%2,%3,%4}, [%5];"
        :: "r"(a), "r"(v.x), "r"(v.y), "r"(v.z), "r"(v.w), "r"(mb) : "memory");
}
__device__ __forceinline__ void st_async32(uint32_t a, uint32_t v, uint32_t mb) {
    asm volatile("st.async.shared::cluster.mbarrier::complete_tx::bytes.b32 [%0], %1, [%2];"
                 :: "r"(a), "r"(v), "r"(mb) : "memory");
}
__device__ __forceinline__ void mb_init(uint32_t a, uint32_t n) {
    asm volatile("mbarrier.init.shared.b64 [%0], %1;" :: "r"(a), "r"(n) : "memory");
}
__device__ __forceinline__ void mb_expect(uint32_t a, uint32_t tx) {
    asm volatile("mbarrier.arrive.expect_tx.shared.b64 _, [%0], %1;"
                 :: "r"(a), "r"(tx) : "memory");
}
__device__ __forceinline__ void mb_wait(uint32_t a, uint32_t par) {
    asm volatile(
        "{\n\t"
        ".reg .pred P;\n\t"
        "WL_%=:\n\t"
        "mbarrier.try_wait.parity.acquire.cta.shared::cta.b64 P, [%0], %1, 0x989680;\n\t"
        "@P bra.uni WD_%=;\n\t"
        "bra.uni WL_%=;\n\t"
        "WD_%=:\n\t"
        "}"
        :: "r"(a), "r"(par) : "memory");
}
__device__ __forceinline__ void barn(int id, int n) {
    asm volatile("bar.sync %0, %1;" :: "r"(id), "r"(n) : "memory");
}
// single-MUFU transcendentals (~5e-4 local err; LSTM gating damps ~100x)
__device__ __forceinline__ float tanhfast(float x) {
    float r; asm("tanh.approx.f32 %0, %1;" : "=f"(r) : "f"(x)); return r;
}
__device__ __forceinline__ float sigf(float x) {
    return fmaf(tanhfast(0.5f * x), 0.5f, 0.5f);
}

// 64-term dot, 8 accumulators (scalar — best measured variant)
#define DOT64(res, w, hv)                                            \
    {                                                                \
        float a0 = 0.f, a1 = 0.f, a2 = 0.f, a3 = 0.f;                \
        float a4 = 0.f, a5 = 0.f, a6 = 0.f, a7 = 0.f;                \
        _Pragma("unroll")                                            \
        for (int k = 0; k < 8; k++) {                                \
            float4 v0 = (hv)[2 * k], v1 = (hv)[2 * k + 1];           \
            a0 = fmaf((w)[8 * k + 0], v0.x, a0);                     \
            a1 = fmaf((w)[8 * k + 1], v0.y, a1);                     \
            a2 = fmaf((w)[8 * k + 2], v0.z, a2);                     \
            a3 = fmaf((w)[8 * k + 3], v0.w, a3);                     \
            a4 = fmaf((w)[8 * k + 4], v1.x, a4);                     \
            a5 = fmaf((w)[8 * k + 5], v1.y, a5);                     \
            a6 = fmaf((w)[8 * k + 6], v1.z, a6);                     \
            a7 = fmaf((w)[8 * k + 7], v1.w, a7);                     \
        }                                                            \
        res = ((a0 + a1) + (a2 + a3)) + ((a4 + a5) + (a6 + a7));     \
    }

// ---------------- kernel ----------------
// 8-CTA cluster per batch; ONE tx-mbarrier per step top (fc + pre + h1).
// R15 structure + dot-window evacuation: during [barn1, bar2] ONLY grp2's
// critical Wih1 dot issues FMA (grp1's pre-dot deferred to after bar2,
// running in warp11's nonlin/send window).
// Warp roles:
//   grp0 (warps 0-3):  wait top -> re-arm (tid0) -> g1a = Whh1.h1[p] -> bar2
//   grp1 (warps 4-7):  step top: y, full local nonlin0 -> s_h0; barn1(256);
//                      bar2(384); THEN pre(t+1) dot -> broadcast (slack)
//   grp2 (warps 8-11): barn1(256) -> Wih1.h0 (critical dot, clean SMSPs) ->
//                      g1b -> bar2(384) -> warp11: nonlin1, fc FIRST, then h1
__global__ void __launch_bounds__(NTH, 1) __cluster_dims__(CSZ, 1, 1)
lstm_decoder_kernel(
    const float* __restrict__ y0,
    const float* __restrict__ h0in,
    const float* __restrict__ c0in,
    const float* __restrict__ wih0,
    const float* __restrict__ whh0,
    const float* __restrict__ bih0,
    const float* __restrict__ bhh0,
    const float* __restrict__ wih1,
    const float* __restrict__ whh1,
    const float* __restrict__ bih1,
    const float* __restrict__ bhh1,
    const float* __restrict__ fcw,
    const float* __restrict__ fcb,
    float* __restrict__ out)
{
    __shared__ __align__(16) float s_h0[2][HID];        // full h0, local
    __shared__ __align__(16) float s_h1[2][HID];        // full h1, via bcast
    __shared__ __align__(16) float s_pre[2][HID][4];    // FULL pre-activations
    __shared__ __align__(16) float s_g1a[SLICE][4];     // [j][gate] (grp0)
    __shared__ __align__(16) float s_g1b[2][SLICE][4];  // [half][j][gate] (grp2)
    __shared__ __align__(16) float s_prest[SLICE][4];   // pre slice staging
    __shared__ __align__(16) float s_h1st[SLICE];
    __shared__ __align__(16) float s_fcp[2][CSZ][4];
    __shared__ __align__(8) unsigned long long s_mb_top[2];

    const int tid  = threadIdx.x;
    const int lane = tid & 31;
    const int wid  = tid >> 5;
    uint32_t rank;
    asm("mov.u32 %0, %%cluster_ctarank;" : "=r"(rank));
    const int b = blockIdx.x >> 3;

    const int grp  = tid >> 7;               // 0:Whh1  1:top/pre  2:Wih1
    const int half = tid & 1;
    const int row  = (tid & 127) >> 1;       // local gate row 0..63
    const int gate = row >> 4;
    const int jloc = row & 15;
    const int grow = gate * HID + (int)rank * SLICE + jloc;

    const uint32_t a_top0 = smem_u32(&s_mb_top[0]);
    const uint32_t a_top1 = smem_u32(&s_mb_top[1]);

    if (tid == 0) {
        mb_init(a_top0, 1);  mb_init(a_top1, 1);
        mb_expect(a_top0, TOP_TX);  mb_expect(a_top1, TOP_TX);
        #pragma unroll
        for (int i = 0; i < CSZ; i++)
            #pragma unroll
            for (int j = 0; j < 4; j++) s_fcp[0][i][j] = 0.0f;
        s_fcp[0][0][0] = y0[b] - fcb[0];     // iter 0 sees y = y0[b]
    }

    // stage full initial h1
    for (int k = tid; k < HID; k += NTH)
        s_h1[0][k] = h0in[BATCH * HID + b * HID + k];

    // prologue: full pre(0) = bias + Whh0 . h0_init (gmem dot, once)
    for (int r = tid; r < 4 * HID; r += NTH) {
        const int g = r >> 7, j = r & 127;
        const float* wr = whh0 + (size_t)r * HID;
        const float* hv = h0in + b * HID;
        float acc = 0.0f;
        #pragma unroll 8
        for (int k = 0; k < HID; k++) acc = fmaf(wr[k], hv[k], acc);
        s_pre[0][j][g] = bih0[r] + bhh0[r] + acc;
    }

    // weights (register-resident, 64 floats per thread)
    float w[64];
    {
        const float* Wsrc = (grp == 0) ? whh1 : (grp == 1) ? whh0 : wih1;
        const float* src  = Wsrc + (size_t)grow * HID + half * 64;
        #pragma unroll
        for (int i = 0; i < 64; i++) w[i] = src[i];
    }
    float bias = 0.0f;
    if (half == 0) {
        if (grp == 0)      bias = bih1[grow] + bhh1[grow];
        else if (grp == 1) bias = bih0[grow] + bhh0[grow];
    }

    // grp1 per-lane nonlin0 state: hidden j = tid-128, FULL vector replicated
    float c0r = 0.0f, wi4[4] = {0, 0, 0, 0};
    if (grp == 1) {
        const int j = tid - 128;
        c0r = c0in[b * HID + j];
        #pragma unroll
        for (int g = 0; g < 4; g++) wi4[g] = wih0[g * HID + j];
    }
    // warp-11 nonlin1 state
    float c1r = 0.0f, fcwr = 0.0f;
    if (wid == 11 && lane < SLICE) {
        c1r  = c0in[BATCH * HID + b * HID + (int)rank * SLICE + lane];
        fcwr = fcw[(int)rank * SLICE + lane];
    }
    const float fc_b = fcb[0];

    // ---- precomputed DSMEM destinations ----
    // grp1: pre slice — thread i=tid&127: dest=((i>>4)+rank)&7, jj=i&15
    uint32_t pdst0 = 0, pdst1 = 0, pmbr0 = 0, pmbr1 = 0;
    if (grp == 1) {
        const int pi    = tid & 127;
        const int pdest = ((pi >> 4) + (int)rank) & 7;
        const int jj    = pi & 15;
        pdst0 = mapa_rank(smem_u32(&s_pre[0][(int)rank * SLICE + jj][0]), pdest);
        pdst1 = mapa_rank(smem_u32(&s_pre[1][(int)rank * SLICE + jj][0]), pdest);
        pmbr0 = mapa_rank(a_top0, pdest);
        pmbr1 = mapa_rank(a_top1, pdest);
    }
    // warp 11: fc + h1 slice — lane: dest=((lane>>2)+rank)&7, qtr=lane&3
    const int dest = ((lane >> 2) + (int)rank) & 7;
    const int qtr  = lane & 3;
    uint32_t fcdst0 = 0, fcdst1 = 0, h1dst0 = 0, h1dst1 = 0, tmbr0 = 0, tmbr1 = 0;
    if (wid == 11) {
        fcdst0 = mapa_rank(smem_u32(&s_fcp[0][rank][qtr]), dest);
        fcdst1 = mapa_rank(smem_u32(&s_fcp[1][rank][qtr]), dest);
        h1dst0 = mapa_rank(smem_u32(&s_h1[0][(int)rank * SLICE]) + 16u * qtr, dest);
        h1dst1 = mapa_rank(smem_u32(&s_h1[1][(int)rank * SLICE]) + 16u * qtr, dest);
        tmbr0  = mapa_rank(a_top0, dest);
        tmbr1  = mapa_rank(a_top1, dest);
    }

    __syncthreads();
    asm volatile("barrier.cluster.arrive.aligned;" ::: "memory");
    asm volatile("barrier.cluster.wait.aligned;" ::: "memory");

    for (int t = 0; t < T_STEPS; t++) {
        const int p = t & 1;
        const int q = p ^ 1;
        const uint32_t a_topp = p ? a_top1 : a_top0;
        const uint32_t par    = (uint32_t)(((t - 1) >> 1) & 1);

        if (grp == 1) {
            // ======== STEP TOP (one wait: fc + pre + h1 all arrived) ========
            if (t > 0) mb_wait(a_topp, par);
            float y;
            {
                const float4* fv = (const float4*)&s_fcp[p][0][0];
                float4 u0 = fv[0], u1 = fv[1], u2 = fv[2], u3 = fv[3];
                float4 u4 = fv[4], u5 = fv[5], u6 = fv[6], u7 = fv[7];
                float t0 = ((u0.x + u0.y) + (u0.z + u0.w)) + ((u1.x + u1.y) + (u1.z + u1.w));
                float t1 = ((u2.x + u2.y) + (u2.z + u2.w)) + ((u3.x + u3.y) + (u3.z + u3.w));
                float t2 = ((u4.x + u4.y) + (u4.z + u4.w)) + ((u5.x + u5.y) + (u5.z + u5.w));
                float t3 = ((u6.x + u6.y) + (u6.z + u6.w)) + ((u7.x + u7.y) + (u7.z + u7.w));
                y = fc_b + ((t0 + t1) + (t2 + t3));
            }
            if (t > 0 && tid == 128 && rank == 0) out[b * T_STEPS + (t - 1)] = y;
            // full local nonlin0: lane j = tid-128
            {
                const int j = tid - 128;
                const float4 pg = *(const float4*)&s_pre[p][j][0];
                float gi = fmaf(wi4[0], y, pg.x);
                float gf = fmaf(wi4[1], y, pg.y);
                float gg = fmaf(wi4[2], y, pg.z);
                float go = fmaf(wi4[3], y, pg.w);
                c0r = sigf(gf) * c0r + sigf(gi) * tanhfast(gg);
                s_h0[p][j] = sigf(go) * tanhfast(c0r);
            }
            barn(1, 256);                    // grp1+grp2: h0 ready
            barn(2, 384);                    // wait out the critical dot window
            // ---- pre(t+1) dot AFTER bar2: no FMA contention with grp2 ----
            float d; DOT64(d, w, (const float4*)&s_h0[p][half * 64]);
            float s = bias + d;
            s += __shfl_xor_sync(0xffffffffu, s, 1);
            if (!half) s_prest[jloc][gate] = s;
            barn(4, 128);                    // grp1 internal
            uint4 v = ((const uint4*)s_prest)[tid & 15];
            st_async128(q ? pdst1 : pdst0, v, q ? pmbr1 : pmbr0);
        } else if (grp == 0) {
            // ---- g1a = bias + Whh1 . h1[p], PARALLEL with grp1's top ----
            if (t > 0) {
                mb_wait(a_topp, par);
                if (tid == 0) mb_expect(a_topp, TOP_TX);   // re-arm (slack warp)
            }
            float d; DOT64(d, w, (const float4*)&s_h1[p][half * 64]);
            float s = bias + d;
            s += __shfl_xor_sync(0xffffffffu, s, 1);
            if (!half) s_g1a[jloc][gate] = s;
            barn(2, 384);                    // publishes g1a to warp11 (early)
        } else {
            // ---- Wih1 . h0 (the ONLY critical dot; clean SMSPs) ----
            barn(1, 256);
            float d; DOT64(d, w, (const float4*)&s_h0[p][half * 64]);
            s_g1b[half][jloc][gate] = d;
            barn(2, 384);                    // grp0/grp1 (long arrived) + grp2

            if (wid == 11) {
                float h1n = 0.0f, fcp = 0.0f;
                if (lane < SLICE) {
                    const float4 A  = *(const float4*)&s_g1a[lane][0];
                    const float4 B0 = *(const float4*)&s_g1b[0][lane][0];
                    const float4 B1 = *(const float4*)&s_g1b[1][lane][0];
                    float gi = A.x + B0.x + B1.x;
                    float gf = A.y + B0.y + B1.y;
                    float gg = A.z + B0.z + B1.z;
                    float go = A.w + B0.w + B1.w;
                    c1r = sigf(gf) * c1r + sigf(gi) * tanhfast(gg);
                    h1n = sigf(go) * tanhfast(c1r);
                    fcp = fcwr * h1n;
                }
                // 3-shfl partial reduce; every lane ends with S[lane&3]
                fcp += __shfl_xor_sync(0xffffffffu, fcp, 8);
                fcp += __shfl_xor_sync(0xffffffffu, fcp, 4);
                fcp  = __shfl_sync(0xffffffffu, fcp, lane & 3);
                // fc partials sent FIRST (critical payload for t+1)
                st_async32(q ? fcdst1 : fcdst0, __float_as_uint(fcp),
                           q ? tmbr1 : tmbr0);
                // h1 payload second (slack side)
                if (lane < SLICE) s_h1st[lane] = h1n;
                __syncwarp();
                uint4 v = ((const uint4*)s_h1st)[qtr];
                st_async128(q ? h1dst1 : h1dst0, v, q ? tmbr1 : tmbr0);
            }
        }
    }

    // final output (fc of iter T-1 landed in buffer 0, parity 1)
    if (rank == 0 && tid == 128) {
        mb_wait(a_top0, (uint32_t)(((T_STEPS - 1) >> 1) & 1));
        float y = fc_b;
        #pragma unroll
        for (int i = 0; i < CSZ; i++)
            #pragma unroll
            for (int j = 0; j < 4; j++) y += s_fcp[0][i][j];
        out[b * T_STEPS + (T_STEPS - 1)] = y;
    }

    asm volatile("barrier.cluster.arrive.aligned;" ::: "memory");
    asm volatile("barrier.cluster.wait.aligned;" ::: "memory");
}

extern "C" void kernel_launch(void* const* d_in, const int* in_sizes, int n_in,
                              void* d_out, int out_size) {
    (void)in_sizes; (void)n_in; (void)out_size;
    const float* y0    = (const float*)d_in[0];
    const float* h0    = (const float*)d_in[1];
    const float* c0    = (const float*)d_in[2];
    const float* W_ih0 = (const float*)d_in[3];
    const float* W_hh0 = (const float*)d_in[4];
    const float* b_ih0 = (const float*)d_in[5];
    const float* b_hh0 = (const float*)d_in[6];
    const float* W_ih1 = (const float*)d_in[7];
    const float* W_hh1 = (const float*)d_in[8];
    const float* b_ih1 = (const float*)d_in[9];
    const float* b_hh1 = (const float*)d_in[10];
    const float* fc_w  = (const float*)d_in[11];
    const float* fc_b  = (const float*)d_in[12];
    float* out = (float*)d_out;

    lstm_decoder_kernel<<<BATCH * CSZ, NTH>>>(
        y0, h0, c0, W_ih0, W_hh0, b_ih0, b_hh0,
        W_ih1, W_hh1, b_ih1, b_hh1, fc_w, fc_b, out);
}

// round 17
// speedup vs baseline: 1.2093x; 1.0222x over previous
#include <cuda_runtime.h>
#include <cstdint>

#define T_STEPS 8640
#define HID     128
#define BATCH   16
#define CSZ     8
#define SLICE   16          /* HID / CSZ */
#define NTH     384
#define TOP_TX  2688        /* fc 8*4*4B + pre 8*64*4B + h1 8*16*4B */

// ---------------- PTX helpers ----------------
__device__ __forceinline__ uint32_t smem_u32(const void* p) {
    return (uint32_t)__cvta_generic_to_shared(p);
}
__device__ __forceinline__ uint32_t mapa_rank(uint32_t a, uint32_t r) {
    uint32_t d;
    asm volatile("mapa.shared::cluster.u32 %0, %1, %2;" : "=r"(d) : "r"(a), "r"(r));
    return d;
}
__device__ __forceinline__ void st_async128(uint32_t a, uint4 v, uint32_t mb) {
    asm volatile(
        "st.async.shared::cluster.mbarrier::complete_tx::bytes.v4.b32 "
        "[%0], {%1,%2,%3,%4}, [%5];"
        :: "r"(a), "r"(v.x), "r"(v.y), "r"(v.z), "r"(v.w), "r"(mb) : "memory");
}
__device__ __forceinline__ void st_async32(uint32_t a, uint32_t v, uint32_t mb) {
    asm volatile("st.async.shared::cluster.mbarrier::complete_tx::bytes.b32 [%0], %1, [%2];"
                 :: "r"(a), "r"(v), "r"(mb) : "memory");
}
__device__ __forceinline__ void mb_init(uint32_t a, uint32_t n) {
    asm volatile("mbarrier.init.shared.b64 [%0], %1;" :: "r"(a), "r"(n) : "memory");
}
__device__ __forceinline__ void mb_expect(uint32_t a, uint32_t tx) {
    asm volatile("mbarrier.arrive.expect_tx.shared.b64 _, [%0], %1;"
                 :: "r"(a), "r"(tx) : "memory");
}
__device__ __forceinline__ void mb_wait(uint32_t a, uint32_t par) {
    asm volatile(
        "{\n\t"
        ".reg .pred P;\n\t"
        "WL_%=:\n\t"
        "mbarrier.try_wait.parity.acquire.cta.shared::cta.b64 P, [%0], %1, 0x989680;\n\t"
        "@P bra.uni WD_%=;\n\t"
        "bra.uni WL_%=;\n\t"
        "WD_%=:\n\t"
        "}"
        :: "r"(a), "r"(par) : "memory");
}
__device__ __forceinline__ void barn(int id, int n) {
    asm volatile("bar.sync %0, %1;" :: "r"(id), "r"(n) : "memory");
}
// single-MUFU transcendentals (~5e-4 local err; LSTM gating damps ~100x)
__device__ __forceinline__ float tanhfast(float x) {
    float r; asm("tanh.approx.f32 %0, %1;" : "=f"(r) : "f"(x)); return r;
}
__device__ __forceinline__ float sigf(float x) {
    return fmaf(tanhfast(0.5f * x), 0.5f, 0.5f);
}

// 64-term dot, 8 accumulators (scalar — best measured variant)
#define DOT64(res, w, hv)                                            \
    {                                                                \
        float a0 = 0.f, a1 = 0.f, a2 = 0.f, a3 = 0.f;                \
        float a4 = 0.f, a5 = 0.f, a6 = 0.f, a7 = 0.f;                \
        _Pragma("unroll")                                            \
        for (int k = 0; k < 8; k++) {                                \
            float4 v0 = (hv)[2 * k], v1 = (hv)[2 * k + 1];           \
            a0 = fmaf((w)[8 * k + 0], v0.x, a0);                     \
            a1 = fmaf((w)[8 * k + 1], v0.y, a1);                     \
            a2 = fmaf((w)[8 * k + 2], v0.z, a2);                     \
            a3 = fmaf((w)[8 * k + 3], v0.w, a3);                     \
            a4 = fmaf((w)[8 * k + 4], v1.x, a4);                     \
            a5 = fmaf((w)[8 * k + 5], v1.y, a5);                     \
            a6 = fmaf((w)[8 * k + 6], v1.z, a6);                     \
            a7 = fmaf((w)[8 * k + 7], v1.w, a7);                     \
        }                                                            \
        res = ((a0 + a1) + (a2 + a3)) + ((a4 + a5) + (a6 + a7));     \
    }

// ---------------- kernel ----------------
// 8-CTA cluster per batch; ONE tx-mbarrier per step top (fc + pre + h1).
// R16 structure + warp11 tail cut: nonlin1 duplicated on all 32 lanes
// (lanes 16-31 mirror lanes 0-15 with replicated c1 state) so the fc
// reduction needs only TWO xor shfls — every lane then holds S[lane&3].
// Warp roles:
//   grp0 (warps 0-3):  wait top -> re-arm (tid0) -> g1a = Whh1.h1[p] -> bar2
//   grp1 (warps 4-7):  step top: y, full local nonlin0 -> s_h0; barn1(256);
//                      bar2(384); THEN pre(t+1) dot -> broadcast (slack)
//   grp2 (warps 8-11): barn1(256) -> Wih1.h0 (critical dot, clean SMSPs) ->
//                      g1b -> bar2(384) -> warp11: nonlin1 x32, fc FIRST, h1
__global__ void __launch_bounds__(NTH, 1) __cluster_dims__(CSZ, 1, 1)
lstm_decoder_kernel(
    const float* __restrict__ y0,
    const float* __restrict__ h0in,
    const float* __restrict__ c0in,
    const float* __restrict__ wih0,
    const float* __restrict__ whh0,
    const float* __restrict__ bih0,
    const float* __restrict__ bhh0,
    const float* __restrict__ wih1,
    const float* __restrict__ whh1,
    const float* __restrict__ bih1,
    const float* __restrict__ bhh1,
    const float* __restrict__ fcw,
    const float* __restrict__ fcb,
    float* __restrict__ out)
{
    __shared__ __align__(16) float s_h0[2][HID];        // full h0, local
    __shared__ __align__(16) float s_h1[2][HID];        // full h1, via bcast
    __shared__ __align__(16) float s_pre[2][HID][4];    // FULL pre-activations
    __shared__ __align__(16) float s_g1a[SLICE][4];     // [j][gate] (grp0)
    __shared__ __align__(16) float s_g1b[2][SLICE][4];  // [half][j][gate] (grp2)
    __shared__ __align__(16) float s_prest[SLICE][4];   // pre slice staging
    __shared__ __align__(16) float s_h1st[SLICE];
    __shared__ __align__(16) float s_fcp[2][CSZ][4];
    __shared__ __align__(8) unsigned long long s_mb_top[2];

    const int tid  = threadIdx.x;
    const int lane = tid & 31;
    const int wid  = tid >> 5;
    uint32_t rank;
    asm("mov.u32 %0, %%cluster_ctarank;" : "=r"(rank));
    const int b = blockIdx.x >> 3;

    const int grp  = tid >> 7;               // 0:Whh1  1:top/pre  2:Wih1
    const int half = tid & 1;
    const int row  = (tid & 127) >> 1;       // local gate row 0..63
    const int gate = row >> 4;
    const int jloc = row & 15;
    const int grow = gate * HID + (int)rank * SLICE + jloc;

    const uint32_t a_top0 = smem_u32(&s_mb_top[0]);
    const uint32_t a_top1 = smem_u32(&s_mb_top[1]);

    if (tid == 0) {
        mb_init(a_top0, 1);  mb_init(a_top1, 1);
        mb_expect(a_top0, TOP_TX);  mb_expect(a_top1, TOP_TX);
        #pragma unroll
        for (int i = 0; i < CSZ; i++)
            #pragma unroll
            for (int j = 0; j < 4; j++) s_fcp[0][i][j] = 0.0f;
        s_fcp[0][0][0] = y0[b] - fcb[0];     // iter 0 sees y = y0[b]
    }

    // stage full initial h1
    for (int k = tid; k < HID; k += NTH)
        s_h1[0][k] = h0in[BATCH * HID + b * HID + k];

    // prologue: full pre(0) = bias + Whh0 . h0_init (gmem dot, once)
    for (int r = tid; r < 4 * HID; r += NTH) {
        const int g = r >> 7, j = r & 127;
        const float* wr = whh0 + (size_t)r * HID;
        const float* hv = h0in + b * HID;
        float acc = 0.0f;
        #pragma unroll 8
        for (int k = 0; k < HID; k++) acc = fmaf(wr[k], hv[k], acc);
        s_pre[0][j][g] = bih0[r] + bhh0[r] + acc;
    }

    // weights (register-resident, 64 floats per thread)
    float w[64];
    {
        const float* Wsrc = (grp == 0) ? whh1 : (grp == 1) ? whh0 : wih1;
        const float* src  = Wsrc + (size_t)grow * HID + half * 64;
        #pragma unroll
        for (int i = 0; i < 64; i++) w[i] = src[i];
    }
    float bias = 0.0f;
    if (half == 0) {
        if (grp == 0)      bias = bih1[grow] + bhh1[grow];
        else if (grp == 1) bias = bih0[grow] + bhh0[grow];
    }

    // grp1 per-lane nonlin0 state: hidden j = tid-128, FULL vector replicated
    float c0r = 0.0f, wi4[4] = {0, 0, 0, 0};
    if (grp == 1) {
        const int j = tid - 128;
        c0r = c0in[b * HID + j];
        #pragma unroll
        for (int g = 0; g < 4; g++) wi4[g] = wih0[g * HID + j];
    }
    // warp-11 nonlin1 state: ALL 32 lanes (lanes 16-31 mirror lanes 0-15)
    float c1r = 0.0f, fcwr = 0.0f;
    if (wid == 11) {
        const int jl = lane & 15;
        c1r  = c0in[BATCH * HID + b * HID + (int)rank * SLICE + jl];
        fcwr = fcw[(int)rank * SLICE + jl];
    }
    const float fc_b = fcb[0];

    // ---- precomputed DSMEM destinations ----
    // grp1: pre slice — thread i=tid&127: dest=((i>>4)+rank)&7, jj=i&15
    uint32_t pdst0 = 0, pdst1 = 0, pmbr0 = 0, pmbr1 = 0;
    if (grp == 1) {
        const int pi    = tid & 127;
        const int pdest = ((pi >> 4) + (int)rank) & 7;
        const int jj    = pi & 15;
        pdst0 = mapa_rank(smem_u32(&s_pre[0][(int)rank * SLICE + jj][0]), pdest);
        pdst1 = mapa_rank(smem_u32(&s_pre[1][(int)rank * SLICE + jj][0]), pdest);
        pmbr0 = mapa_rank(a_top0, pdest);
        pmbr1 = mapa_rank(a_top1, pdest);
    }
    // warp 11: fc + h1 slice — lane: dest=((lane>>2)+rank)&7, qtr=lane&3
    const int dest = ((lane >> 2) + (int)rank) & 7;
    const int qtr  = lane & 3;
    uint32_t fcdst0 = 0, fcdst1 = 0, h1dst0 = 0, h1dst1 = 0, tmbr0 = 0, tmbr1 = 0;
    if (wid == 11) {
        fcdst0 = mapa_rank(smem_u32(&s_fcp[0][rank][qtr]), dest);
        fcdst1 = mapa_rank(smem_u32(&s_fcp[1][rank][qtr]), dest);
        h1dst0 = mapa_rank(smem_u32(&s_h1[0][(int)rank * SLICE]) + 16u * qtr, dest);
        h1dst1 = mapa_rank(smem_u32(&s_h1[1][(int)rank * SLICE]) + 16u * qtr, dest);
        tmbr0  = mapa_rank(a_top0, dest);
        tmbr1  = mapa_rank(a_top1, dest);
    }

    __syncthreads();
    asm volatile("barrier.cluster.arrive.aligned;" ::: "memory");
    asm volatile("barrier.cluster.wait.aligned;" ::: "memory");

    for (int t = 0; t < T_STEPS; t++) {
        const int p = t & 1;
        const int q = p ^ 1;
        const uint32_t a_topp = p ? a_top1 : a_top0;
        const uint32_t par    = (uint32_t)(((t - 1) >> 1) & 1);

        if (grp == 1) {
            // ======== STEP TOP (one wait: fc + pre + h1 all arrived) ========
            if (t > 0) mb_wait(a_topp, par);
            float y;
            {
                const float4* fv = (const float4*)&s_fcp[p][0][0];
                float4 u0 = fv[0], u1 = fv[1], u2 = fv[2], u3 = fv[3];
                float4 u4 = fv[4], u5 = fv[5], u6 = fv[6], u7 = fv[7];
                float t0 = ((u0.x + u0.y) + (u0.z + u0.w)) + ((u1.x + u1.y) + (u1.z + u1.w));
                float t1 = ((u2.x + u2.y) + (u2.z + u2.w)) + ((u3.x + u3.y) + (u3.z + u3.w));
                float t2 = ((u4.x + u4.y) + (u4.z + u4.w)) + ((u5.x + u5.y) + (u5.z + u5.w));
                float t3 = ((u6.x + u6.y) + (u6.z + u6.w)) + ((u7.x + u7.y) + (u7.z + u7.w));
                y = fc_b + ((t0 + t1) + (t2 + t3));
            }
            if (t > 0 && tid == 128 && rank == 0) out[b * T_STEPS + (t - 1)] = y;
            // full local nonlin0: lane j = tid-128
            {
                const int j = tid - 128;
                const float4 pg = *(const float4*)&s_pre[p][j][0];
                float gi = fmaf(wi4[0], y, pg.x);
                float gf = fmaf(wi4[1], y, pg.y);
                float gg = fmaf(wi4[2], y, pg.z);
                float go = fmaf(wi4[3], y, pg.w);
                c0r = sigf(gf) * c0r + sigf(gi) * tanhfast(gg);
                s_h0[p][j] = sigf(go) * tanhfast(c0r);
            }
            barn(1, 256);                    // grp1+grp2: h0 ready
            barn(2, 384);                    // wait out the critical dot window
            // ---- pre(t+1) dot AFTER bar2: no FMA contention with grp2 ----
            float d; DOT64(d, w, (const float4*)&s_h0[p][half * 64]);
            float s = bias + d;
            s += __shfl_xor_sync(0xffffffffu, s, 1);
            if (!half) s_prest[jloc][gate] = s;
            barn(4, 128);                    // grp1 internal
            uint4 v = ((const uint4*)s_prest)[tid & 15];
            st_async128(q ? pdst1 : pdst0, v, q ? pmbr1 : pmbr0);
        } else if (grp == 0) {
            // ---- g1a = bias + Whh1 . h1[p], PARALLEL with grp1's top ----
            if (t > 0) {
                mb_wait(a_topp, par);
                if (tid == 0) mb_expect(a_topp, TOP_TX);   // re-arm (slack warp)
            }
            float d; DOT64(d, w, (const float4*)&s_h1[p][half * 64]);
            float s = bias + d;
            s += __shfl_xor_sync(0xffffffffu, s, 1);
            if (!half) s_g1a[jloc][gate] = s;
            barn(2, 384);                    // publishes g1a to warp11 (early)
        } else {
            // ---- Wih1 . h0 (the ONLY critical dot; clean SMSPs) ----
            barn(1, 256);
            float d; DOT64(d, w, (const float4*)&s_h0[p][half * 64]);
            s_g1b[half][jloc][gate] = d;
            barn(2, 384);                    // grp0/grp1 (long arrived) + grp2

            if (wid == 11) {
                // nonlin1 on ALL 32 lanes (16-31 mirror; LDS broadcast free)
                const int jl = lane & 15;
                const float4 A  = *(const float4*)&s_g1a[jl][0];
                const float4 B0 = *(const float4*)&s_g1b[0][jl][0];
                const float4 B1 = *(const float4*)&s_g1b[1][jl][0];
                float gi = A.x + B0.x + B1.x;
                float gf = A.y + B0.y + B1.y;
                float gg = A.z + B0.z + B1.z;
                float go = A.w + B0.w + B1.w;
                c1r = sigf(gf) * c1r + sigf(gi) * tanhfast(gg);
                float h1n = sigf(go) * tanhfast(c1r);
                if (lane < SLICE) s_h1st[lane] = h1n;   // issue early (slack)
                float fcp = fcwr * h1n;
                // TWO xor shfls: every lane's group {L,L^4,L^8,L^12} covers
                // j = lane mod 4 exactly once within its 16-lane half
                fcp += __shfl_xor_sync(0xffffffffu, fcp, 8);
                fcp += __shfl_xor_sync(0xffffffffu, fcp, 4);
                // fc partials sent FIRST (critical payload for t+1)
                st_async32(q ? fcdst1 : fcdst0, __float_as_uint(fcp),
                           q ? tmbr1 : tmbr0);
                // h1 payload second (slack side)
                __syncwarp();
                uint4 v = ((const uint4*)s_h1st)[qtr];
                st_async128(q ? h1dst1 : h1dst0, v, q ? tmbr1 : tmbr0);
            }
        }
    }

    // final output (fc of iter T-1 landed in buffer 0, parity 1)
    if (rank == 0 && tid == 128) {
        mb_wait(a_top0, (uint32_t)(((T_STEPS - 1) >> 1) & 1));
        float y = fc_b;
        #pragma unroll
        for (int i = 0; i < CSZ; i++)
            #pragma unroll
            for (int j = 0; j < 4; j++) y += s_fcp[0][i][j];
        out[b * T_STEPS + (T_STEPS - 1)] = y;
    }

    asm volatile("barrier.cluster.arrive.aligned;" ::: "memory");
    asm volatile("barrier.cluster.wait.aligned;" ::: "memory");
}

extern "C" void kernel_launch(void* const* d_in, const int* in_sizes, int n_in,
                              void* d_out, int out_size) {
    (void)in_sizes; (void)n_in; (void)out_size;
    const float* y0    = (const float*)d_in[0];
    const float* h0    = (const float*)d_in[1];
    const float* c0    = (const float*)d_in[2];
    const float* W_ih0 = (const float*)d_in[3];
    const float* W_hh0 = (const float*)d_in[4];
    const float* b_ih0 = (const float*)d_in[5];
    const float* b_hh0 = (const float*)d_in[6];
    const float* W_ih1 = (const float*)d_in[7];
    const float* W_hh1 = (const float*)d_in[8];
    const float* b_ih1 = (const float*)d_in[9];
    const float* b_hh1 = (const float*)d_in[10];
    const float* fc_w  = (const float*)d_in[11];
    const float* fc_b  = (const float*)d_in[12];
    float* out = (float*)d_out;

    lstm_decoder_kernel<<<BATCH * CSZ, NTH>>>(
        y0, h0, c0, W_ih0, W_hh0, b_ih0, b_hh0,
        W_ih1, W_hh1, b_ih1, b_hh1, fc_w, fc_b, out);
}